// round 1
// baseline (speedup 1.0000x reference)
#include <cuda_runtime.h>

#define THREADS 256
#define ROWS    64
#define IN_DIM  2304
#define OUT_DIM 576
#define BATCH   16384

// Per-group tiled block-diagonal GEMM.
// Each CTA owns ROWS=64 batch rows. Threads: r = tid>>2 (row), q = tid&3
// (column-quarter). For a group (SIZE -> CHOICE), thread computes outputs
// j = jj*4 + q, jj in [0, CHOICE/4).
//
// Smem:
//  Xs: [ROWS][SIZE+4] floats (pad 4 keeps 16B alignment and makes the 8
//      distinct row addresses per warp land on disjoint 16B bank groups ->
//      1-phase LDS.128).
//  Wt: k4-interleaved transpose, float4 element (k4, j) = W[4k4..4k4+3][j].
//      Warp reads 4 consecutive-j float4s (64B contiguous) -> 1 phase.
template<int SIZE, int CHOICE>
__device__ __forceinline__ void run_segment(
    const float* __restrict__ x, const float* __restrict__ w,
    const float* __restrict__ bias, float* __restrict__ out,
    int row0, int ngroups, int t_off0, int w_off0, int o_off0,
    float* Xs, float* Wt)
{
    const int tid = threadIdx.x;
    constexpr int XST = SIZE + 4;            // X smem row stride (floats)
    constexpr int SV  = SIZE / 4;            // float4 per X row
    constexpr int NXV = ROWS * SV;           // float4 in X tile
    constexpr int XPT = (NXV + THREADS - 1) / THREADS;
    constexpr int NW  = SIZE * CHOICE;       // floats in W block
    constexpr int WPT = (NW + THREADS - 1) / THREADS;
    constexpr int JT  = CHOICE / 4;          // outputs per thread

    float4 xreg[XPT];
    float  wreg[WPT];

    // ---- prefetch group 0 into registers (overlaps prior segment's tail) ----
    {
        const float* xg = x + (size_t)row0 * IN_DIM + t_off0;
        #pragma unroll
        for (int u = 0; u < XPT; u++) {
            int i = tid + u * THREADS;
            if (i < NXV) {
                int r = i / SV, c4 = i % SV;
                xreg[u] = *reinterpret_cast<const float4*>(xg + (size_t)r * IN_DIM + c4 * 4);
            }
        }
        #pragma unroll
        for (int u = 0; u < WPT; u++) {
            int i = tid + u * THREADS;
            if (i < NW) wreg[u] = w[w_off0 + i];
        }
    }

    for (int g = 0; g < ngroups; g++) {
        __syncthreads();   // previous compute finished; smem reusable

        // ---- registers -> smem ----
        #pragma unroll
        for (int u = 0; u < XPT; u++) {
            int i = tid + u * THREADS;
            if (i < NXV) {
                int r = i / SV, c4 = i % SV;
                *reinterpret_cast<float4*>(&Xs[r * XST + c4 * 4]) = xreg[u];
            }
        }
        #pragma unroll
        for (int u = 0; u < WPT; u++) {
            int i = tid + u * THREADS;
            if (i < NW) {
                int j = i % CHOICE, k = i / CHOICE;
                Wt[((k >> 2) * CHOICE + j) * 4 + (k & 3)] = wreg[u];
            }
        }

        // ---- prefetch group g+1 (LDG latency hides behind compute of g) ----
        if (g + 1 < ngroups) {
            const float* xg = x + (size_t)row0 * IN_DIM + t_off0 + (g + 1) * SIZE;
            #pragma unroll
            for (int u = 0; u < XPT; u++) {
                int i = tid + u * THREADS;
                if (i < NXV) {
                    int r = i / SV, c4 = i % SV;
                    xreg[u] = *reinterpret_cast<const float4*>(xg + (size_t)r * IN_DIM + c4 * 4);
                }
            }
            int wo = w_off0 + (g + 1) * NW;
            #pragma unroll
            for (int u = 0; u < WPT; u++) {
                int i = tid + u * THREADS;
                if (i < NW) wreg[u] = w[wo + i];
            }
        }

        __syncthreads();   // smem tile ready

        // ---- compute ----
        const int r = tid >> 2;
        const int q = tid & 3;
        float acc[JT];
        #pragma unroll
        for (int jj = 0; jj < JT; jj++) acc[jj] = 0.f;

        const float4* Xr = reinterpret_cast<const float4*>(&Xs[r * XST]);
        const float4* W4 = reinterpret_cast<const float4*>(Wt);
        #pragma unroll
        for (int k4 = 0; k4 < SV; k4++) {
            float4 xv = Xr[k4];
            #pragma unroll
            for (int jj = 0; jj < JT; jj++) {
                float4 wv = W4[k4 * CHOICE + (jj * 4 + q)];
                acc[jj] += xv.x * wv.x;
                acc[jj] += xv.y * wv.y;
                acc[jj] += xv.z * wv.z;
                acc[jj] += xv.w * wv.w;
            }
        }

        const int o_off = o_off0 + g * CHOICE;
        float* orow = out + (size_t)(row0 + r) * OUT_DIM + o_off;
        #pragma unroll
        for (int jj = 0; jj < JT; jj++) {
            int j = jj * 4 + q;
            orow[j] = acc[jj] + bias[o_off + j];
        }
    }
}

extern "C" __global__ void __launch_bounds__(THREADS)
tet_kernel(const float* __restrict__ x, const float* __restrict__ w,
           const float* __restrict__ bias, float* __restrict__ out)
{
    __shared__ __align__(16) float Xs[ROWS * 68];   // max stride 68 (SIZE=64)
    __shared__ __align__(16) float Wt[1024];        // max 64*16 floats

    const int row0 = blockIdx.x * ROWS;

    // Segment 1: 16 groups of (16 -> 4):  t 0..255,   w 0..1023,    o 0..63
    run_segment<16, 4 >(x, w, bias, out, row0, 16,    0,    0,   0, Xs, Wt);
    // Segment 2: 32 groups of (32 -> 8):  t 256..1279, w 1024..9215, o 64..319
    run_segment<32, 8 >(x, w, bias, out, row0, 32,  256, 1024,  64, Xs, Wt);
    // Segment 3: 16 groups of (64 -> 16): t 1280..2303, w 9216..25599, o 320..575
    run_segment<64, 16>(x, w, bias, out, row0, 16, 1280, 9216, 320, Xs, Wt);
}

extern "C" void kernel_launch(void* const* d_in, const int* in_sizes, int n_in,
                              void* d_out, int out_size)
{
    const float* x    = (const float*)d_in[0];
    const float* wflt = (const float*)d_in[1];
    const float* bias = (const float*)d_in[2];
    float* out        = (float*)d_out;

    tet_kernel<<<BATCH / ROWS, THREADS>>>(x, wflt, bias, out);
}

// round 2
// speedup vs baseline: 1.6972x; 1.6972x over previous
#include <cuda_runtime.h>
#include <cstdint>

#define THREADS 256
#define IN_DIM  2304
#define OUT_DIM 576
#define BATCH   16384
#define IN4     576            // float4 per x row
#define RS4     640            // padded row stride in float4 (2560 floats)
#define CHUNK   8              // rows per chunk
#define NCTA    148
#define SMEM_BYTES (2 * CHUNK * RS4 * 16)   // 163840

// group index of a float4 position f (0..575) within one x row
__device__ __forceinline__ int grp_of_f4(int f) {
    return (f < 64) ? (f >> 2)
         : (f < 320 ? 16 + ((f - 64) >> 3)
                    : 48 + ((f - 320) >> 4));
}

__device__ __forceinline__ void cpa16(uint32_t daddr, const void* src) {
    asm volatile("cp.async.cg.shared.global [%0], [%1], 16;\n" :: "r"(daddr), "l"(src));
}

extern "C" __global__ void __launch_bounds__(THREADS, 1)
tet_kernel(const float* __restrict__ x, const float* __restrict__ w,
           const float* __restrict__ bias, float* __restrict__ out)
{
    extern __shared__ __align__(16) float4 Xs[];   // [2][CHUNK][RS4]

    const int tid = threadIdx.x;
    const int bid = blockIdx.x;

    // row partition: 16384 = 148*110 + 104 -> first 104 CTAs get 111 rows
    const int row0  = bid * 110 + (bid < 104 ? bid : 104);
    const int nrows = 110 + (bid < 104 ? 1 : 0);
    const int nchunks = (nrows + CHUNK - 1) / CHUNK;   // 14

    // ---------------- column assignment + W into registers ----------------
    // seg3: column = tid   (group gg3 = tid>>4, j = tid&15)
    // seg2: column = tid   (group gg2 = tid>>3, j = tid&7)
    // seg1: 8 lanes per warp: col1 = warp*8 + (lane&7), active if (lane&31)<8
    const int gg3 = tid >> 4;
    const int gg2 = tid >> 3;
    const bool act1 = (tid & 31) < 8;
    const int c1   = ((tid >> 5) << 3) + (tid & 7);   // 0..63
    const int g1   = c1 >> 2;
    const int j1   = c1 & 3;

    float w3[64], w2[32], w1[16];
    {
        const int wb3 = 9216 + gg3 * 1024 + (tid & 15);
        #pragma unroll
        for (int k = 0; k < 64; k++) w3[k] = w[wb3 + k * 16];
        const int wb2 = 1024 + gg2 * 256 + (tid & 7);
        #pragma unroll
        for (int k = 0; k < 32; k++) w2[k] = w[wb2 + k * 8];
        const int wb1 = g1 * 64 + j1;
        #pragma unroll
        for (int k = 0; k < 16; k++) w1[k] = w[wb1 + k * 4];
    }
    const float b3 = bias[320 + tid];
    const float b2 = bias[64 + tid];
    const float b1 = bias[c1];

    // padded smem float4 offsets of each lane's X segment
    const int off3 = 368 + gg3 * 17;   // (320 + gg3*16) + (48 + gg3)
    const int off2 = 80  + gg2 * 9;    // (64  + gg2*8 ) + (16 + gg2)
    const int off1 = 5 * g1;           // (g1*4) + g1

    // ---------------- staging helper (as a macro-ish lambda) ----------------
    auto stage = [&](int c, int buf) {
        #pragma unroll
        for (int u = 0; u < 18; u++) {               // 18*256 = 4608 = 8 rows * 576 f4
            int idx = tid + u * THREADS;
            int r   = idx / IN4;
            int f   = idx - r * IN4;
            int rl  = c * CHUNK + r;
            if (rl < nrows) {
                int g = grp_of_f4(f);
                float4* dst = Xs + (size_t)buf * (CHUNK * RS4) + r * RS4 + f + g;
                const float* src = x + (size_t)(row0 + rl) * IN_DIM + f * 4;
                cpa16((uint32_t)__cvta_generic_to_shared(dst), src);
            }
        }
    };

    stage(0, 0);
    asm volatile("cp.async.commit_group;\n");

    for (int c = 0; c < nchunks; c++) {
        if (c + 1 < nchunks) stage(c + 1, (c + 1) & 1);
        asm volatile("cp.async.commit_group;\n");
        asm volatile("cp.async.wait_group 1;\n");
        __syncthreads();

        const float4* base = Xs + (size_t)(c & 1) * (CHUNK * RS4);
        #pragma unroll 1
        for (int r = 0; r < CHUNK; r++) {
            int rl = c * CHUNK + r;
            if (rl >= nrows) break;
            const float4* xr = base + r * RS4;

            // seg3: 64 FMAs, 4 chains
            float a0 = 0.f, a1 = 0.f, a2 = 0.f, a3 = 0.f;
            #pragma unroll
            for (int k4 = 0; k4 < 16; k4++) {
                float4 xv = xr[off3 + k4];
                a0 = fmaf(xv.x, w3[4 * k4 + 0], a0);
                a1 = fmaf(xv.y, w3[4 * k4 + 1], a1);
                a2 = fmaf(xv.z, w3[4 * k4 + 2], a2);
                a3 = fmaf(xv.w, w3[4 * k4 + 3], a3);
            }
            // seg2: 32 FMAs, 4 chains
            float p0 = 0.f, p1 = 0.f, p2 = 0.f, p3 = 0.f;
            #pragma unroll
            for (int k4 = 0; k4 < 8; k4++) {
                float4 xv = xr[off2 + k4];
                p0 = fmaf(xv.x, w2[4 * k4 + 0], p0);
                p1 = fmaf(xv.y, w2[4 * k4 + 1], p1);
                p2 = fmaf(xv.z, w2[4 * k4 + 2], p2);
                p3 = fmaf(xv.w, w2[4 * k4 + 3], p3);
            }
            // seg1: 16 FMAs, 4 chains (all lanes compute; only 8/warp store)
            float q0 = 0.f, q1 = 0.f, q2 = 0.f, q3 = 0.f;
            #pragma unroll
            for (int k4 = 0; k4 < 4; k4++) {
                float4 xv = xr[off1 + k4];
                q0 = fmaf(xv.x, w1[4 * k4 + 0], q0);
                q1 = fmaf(xv.y, w1[4 * k4 + 1], q1);
                q2 = fmaf(xv.z, w1[4 * k4 + 2], q2);
                q3 = fmaf(xv.w, w1[4 * k4 + 3], q3);
            }

            float* orow = out + (size_t)(row0 + rl) * OUT_DIM;
            orow[320 + tid] = (a0 + a1) + (a2 + a3) + b3;
            orow[64 + tid]  = (p0 + p1) + (p2 + p3) + b2;
            if (act1) orow[c1] = (q0 + q1) + (q2 + q3) + b1;
        }
        __syncthreads();
    }
}

extern "C" void kernel_launch(void* const* d_in, const int* in_sizes, int n_in,
                              void* d_out, int out_size)
{
    const float* x    = (const float*)d_in[0];
    const float* wflt = (const float*)d_in[1];
    const float* bias = (const float*)d_in[2];
    float* out        = (float*)d_out;

    cudaFuncSetAttribute(tet_kernel, cudaFuncAttributeMaxDynamicSharedMemorySize, SMEM_BYTES);
    tet_kernel<<<NCTA, THREADS, SMEM_BYTES>>>(x, wflt, bias, out);
}

// round 3
// speedup vs baseline: 1.7041x; 1.0040x over previous
#include <cuda_runtime.h>
#include <cstdint>

#define THREADS 512
#define IN_DIM  2304
#define OUT_DIM 576
#define BATCH   16384
#define IN4     576            // float4 per compact x row
#define RS4     656            // padded row stride in float4
#define CHUNK   8              // rows per chunk
#define NCTA    148
#define SMEM_BYTES (2 * CHUNK * RS4 * 16)   // 167936

// Padded smem row layout (float4 indices):
//   seg1: 16 groups, stride 5  -> [0, 80)
//   seg2: 32 groups, stride 10 -> [80, 400)   (stride ≡ 2 mod 8 f4: the two
//         groups a warp touches sit on disjoint bank octets -> 1-phase LDS)
//   seg3: 16 groups, stride 16 -> [400, 656)  (one group per warp)
__device__ __forceinline__ int pad_map(int f) {
    if (f < 64)  return f + (f >> 2);
    if (f < 320) return 80 + (f - 64) + (((f - 64) >> 3) << 1);
    return 400 + (f - 320);
}

__device__ __forceinline__ void cpa16(uint32_t daddr, const void* src) {
    asm volatile("cp.async.cg.shared.global [%0], [%1], 16;\n" :: "r"(daddr), "l"(src));
}

extern "C" __global__ void __launch_bounds__(THREADS, 1)
tet_kernel(const float* __restrict__ x, const float* __restrict__ w,
           const float* __restrict__ bias, float* __restrict__ out)
{
    extern __shared__ __align__(16) float4 Xs[];   // [2][CHUNK][RS4]

    const int tid = threadIdx.x;
    const int bid = blockIdx.x;

    // row partition: 16384 = 148*110 + 104 -> first 104 CTAs get 111 rows
    const int row0  = bid * 110 + (bid < 104 ? bid : 104);
    const int nrows = 110 + (bid < 104 ? 1 : 0);
    const int nchunks = (nrows + CHUNK - 1) / CHUNK;

    // -------- column assignment: lane pair (even,odd) splits K ----------
    const int h   = tid & 1;        // K-half parity
    const int col = tid >> 1;       // 0..255

    const int gg3 = col >> 4, j3 = col & 15;
    const int gg2 = col >> 3, j2 = col & 7;
    const bool act1 = tid < 128;    // seg1: columns 0..63
    const int c1 = act1 ? col : 0;
    const int g1 = c1 >> 2, j1 = c1 & 3;

    // K-interleave: thread parity h owns f4 indices {2*k4 + h} within its
    // group, i.e. k = 8*k4 + 4*h + (0..3).
    float w3[32], w2[16], w1[8];
    {
        const int wb3 = 9216 + gg3 * 1024 + j3;
        #pragma unroll
        for (int kp = 0; kp < 32; kp++) {
            int k = 8 * (kp >> 2) + 4 * h + (kp & 3);
            w3[kp] = w[wb3 + k * 16];
        }
        const int wb2 = 1024 + gg2 * 256 + j2;
        #pragma unroll
        for (int kp = 0; kp < 16; kp++) {
            int k = 8 * (kp >> 2) + 4 * h + (kp & 3);
            w2[kp] = w[wb2 + k * 8];
        }
        const int wb1 = g1 * 64 + j1;
        #pragma unroll
        for (int kp = 0; kp < 8; kp++) {
            int k = 8 * (kp >> 2) + 4 * h + (kp & 3);
            w1[kp] = w[wb1 + k * 4];
        }
    }
    const float b3 = bias[320 + col];
    const float b2 = bias[64 + col];
    const float b1 = bias[c1];

    const int off3 = 400 + gg3 * 16;
    const int off2 = 80  + gg2 * 10;
    const int off1 = 5 * g1;

    // -------------------------- staging --------------------------------
    auto stage = [&](int c, int buf) {
        #pragma unroll
        for (int u = 0; u < 9; u++) {            // 9*512 = 4608 = 8 rows * 576
            int idx = tid + u * THREADS;
            int r   = idx / IN4;
            int f   = idx - r * IN4;
            int rl  = c * CHUNK + r;
            if (rl < nrows) {
                float4* dst = Xs + (size_t)buf * (CHUNK * RS4) + r * RS4 + pad_map(f);
                const float* src = x + (size_t)(row0 + rl) * IN_DIM + f * 4;
                cpa16((uint32_t)__cvta_generic_to_shared(dst), src);
            }
        }
    };

    stage(0, 0);
    asm volatile("cp.async.commit_group;\n");

    for (int c = 0; c < nchunks; c++) {
        if (c + 1 < nchunks) stage(c + 1, (c + 1) & 1);
        asm volatile("cp.async.commit_group;\n");
        asm volatile("cp.async.wait_group 1;\n");
        __syncthreads();

        const float4* base = Xs + (size_t)(c & 1) * (CHUNK * RS4);
        const int rmax = min(CHUNK, nrows - c * CHUNK);
        #pragma unroll 1
        for (int r = 0; r < rmax; r++) {
            const float4* xr = base + r * RS4;

            // seg3: 8 LDS.128 + 32 FMA (half-K)
            float a0 = 0.f, a1 = 0.f, a2 = 0.f, a3 = 0.f;
            #pragma unroll
            for (int k4 = 0; k4 < 8; k4++) {
                float4 xv = xr[off3 + 2 * k4 + h];
                a0 = fmaf(xv.x, w3[4 * k4 + 0], a0);
                a1 = fmaf(xv.y, w3[4 * k4 + 1], a1);
                a2 = fmaf(xv.z, w3[4 * k4 + 2], a2);
                a3 = fmaf(xv.w, w3[4 * k4 + 3], a3);
            }
            float s3 = (a0 + a1) + (a2 + a3);
            s3 += __shfl_xor_sync(0xffffffffu, s3, 1);

            // seg2: 4 LDS.128 + 16 FMA
            float p0 = 0.f, p1 = 0.f, p2 = 0.f, p3 = 0.f;
            #pragma unroll
            for (int k4 = 0; k4 < 4; k4++) {
                float4 xv = xr[off2 + 2 * k4 + h];
                p0 = fmaf(xv.x, w2[4 * k4 + 0], p0);
                p1 = fmaf(xv.y, w2[4 * k4 + 1], p1);
                p2 = fmaf(xv.z, w2[4 * k4 + 2], p2);
                p3 = fmaf(xv.w, w2[4 * k4 + 3], p3);
            }
            float s2 = (p0 + p1) + (p2 + p3);
            s2 += __shfl_xor_sync(0xffffffffu, s2, 1);

            // seg1: 2 LDS.128 + 8 FMA (only threads 0..127 store)
            float q0 = 0.f, q1 = 0.f, q2 = 0.f, q3 = 0.f;
            #pragma unroll
            for (int k4 = 0; k4 < 2; k4++) {
                float4 xv = xr[off1 + 2 * k4 + h];
                q0 = fmaf(xv.x, w1[4 * k4 + 0], q0);
                q1 = fmaf(xv.y, w1[4 * k4 + 1], q1);
                q2 = fmaf(xv.z, w1[4 * k4 + 2], q2);
                q3 = fmaf(xv.w, w1[4 * k4 + 3], q3);
            }
            float s1 = (q0 + q1) + (q2 + q3);
            s1 += __shfl_xor_sync(0xffffffffu, s1, 1);

            float* orow = out + (size_t)(row0 + c * CHUNK + r) * OUT_DIM;
            if (h == 0) {
                orow[320 + col] = s3 + b3;
                if (act1) orow[c1] = s1 + b1;
            } else {
                orow[64 + col] = s2 + b2;
            }
        }
        __syncthreads();
    }
}

extern "C" void kernel_launch(void* const* d_in, const int* in_sizes, int n_in,
                              void* d_out, int out_size)
{
    const float* x    = (const float*)d_in[0];
    const float* wflt = (const float*)d_in[1];
    const float* bias = (const float*)d_in[2];
    float* out        = (float*)d_out;

    cudaFuncSetAttribute(tet_kernel, cudaFuncAttributeMaxDynamicSharedMemorySize, SMEM_BYTES);
    tet_kernel<<<NCTA, THREADS, SMEM_BYTES>>>(x, wflt, bias, out);
}

// round 4
// speedup vs baseline: 1.7090x; 1.0029x over previous
#include <cuda_runtime.h>
#include <cstdint>

#define THREADS 512
#define IN_DIM  2304
#define OUT_DIM 576
#define BATCH   16384
#define IN4     576            // float4 per compact x row
#define RS4     688            // padded row stride in float4
#define CHUNK   8              // rows per chunk
#define NCTA    148
#define SMEM_BYTES (2 * CHUNK * RS4 * 16)   // 176128

// Padded smem row layout (float4 indices):
//   seg1: 16 groups, stride 5  -> [0, 80)
//   seg2: 32 groups, stride 10 -> [80, 400)    (10 ≡ 2 mod 8)
//   seg3: 16 groups, stride 18 -> [400, 688)   (18 ≡ 2 mod 8)
__device__ __forceinline__ int pad_map(int f) {
    if (f < 64)  return f + (f >> 2);
    if (f < 320) return 80 + (f - 64) + (((f - 64) >> 3) << 1);
    return 400 + (f - 320) + (((f - 320) >> 4) << 1);
}

__device__ __forceinline__ void cpa16(uint32_t daddr, const void* src) {
    asm volatile("cp.async.cg.shared.global [%0], [%1], 16;\n" :: "r"(daddr), "l"(src));
}

extern "C" __global__ void __launch_bounds__(THREADS, 1)
tet_kernel(const float* __restrict__ x, const float* __restrict__ w,
           const float* __restrict__ bias, float* __restrict__ out)
{
    extern __shared__ __align__(16) float4 Xs[];   // [2][CHUNK][RS4]

    const int tid = threadIdx.x;
    const int bid = blockIdx.x;

    // row partition: 16384 = 148*110 + 104
    const int row0  = bid * 110 + (bid < 104 ? bid : 104);
    const int nrows = 110 + (bid < 104 ? 1 : 0);
    const int nchunks = (nrows + CHUNK - 1) / CHUNK;

    const int h = tid & 1;          // K-half parity (partner = tid^1)

    // Per-thread role:
    //  tid <  256 : seg3  g3 = tid>>4, col pair (cp, cp+8), cp=(tid>>1)&7, half-K
    //  tid >= 256 : seg2  g2 = (tid-256)>>3, col pair (cp2, cp2+4), half-K
    //  tid >= 448 : + seg1 g1 = (tid-448)>>2, col pair (cp1, cp1+2), half-K
    const bool is3 = tid < 256;
    const int g3  = tid >> 4;
    const int cp3 = (tid >> 1) & 7;
    const int u2  = (tid - 256) & 255;
    const int g2  = u2 >> 3;
    const int cp2 = (u2 >> 1) & 3;
    const bool is1 = tid >= 448;
    const int v1  = (tid - 448) & 63;
    const int g1  = v1 >> 2;
    const int cp1 = (v1 >> 1) & 1;

    // ---- W into registers (K-interleaved: this thread owns k = 8*k4+4*h+i) ----
    float wa[32], wb[32];   // seg3 uses [0..31]; seg2 uses [0..15]
    float wc[8],  wd[8];    // seg1
    float bA, bB, bC = 0.f, bD = 0.f;
    int colA, colB, colC = 0, colD = 0;

    if (is3) {
        const int base = 9216 + g3 * 1024;
        #pragma unroll
        for (int k4 = 0; k4 < 8; k4++)
            #pragma unroll
            for (int i = 0; i < 4; i++) {
                int k = 8 * k4 + 4 * h + i;
                wa[4 * k4 + i] = w[base + k * 16 + cp3];
                wb[4 * k4 + i] = w[base + k * 16 + cp3 + 8];
            }
        colA = 320 + g3 * 16 + cp3;
        colB = colA + 8;
        bA = bias[colA]; bB = bias[colB];
    } else {
        const int base = 1024 + g2 * 256;
        #pragma unroll
        for (int k4 = 0; k4 < 4; k4++)
            #pragma unroll
            for (int i = 0; i < 4; i++) {
                int k = 8 * k4 + 4 * h + i;
                wa[4 * k4 + i] = w[base + k * 8 + cp2];
                wb[4 * k4 + i] = w[base + k * 8 + cp2 + 4];
            }
        colA = 64 + g2 * 8 + cp2;
        colB = colA + 4;
        bA = bias[colA]; bB = bias[colB];
        if (is1) {
            const int b1 = g1 * 64;
            #pragma unroll
            for (int k4 = 0; k4 < 2; k4++)
                #pragma unroll
                for (int i = 0; i < 4; i++) {
                    int k = 8 * k4 + 4 * h + i;
                    wc[4 * k4 + i] = w[b1 + k * 4 + cp1];
                    wd[4 * k4 + i] = w[b1 + k * 4 + cp1 + 2];
                }
            colC = g1 * 4 + cp1;
            colD = colC + 2;
            bC = bias[colC]; bD = bias[colD];
        }
    }

    const int off3 = 400 + g3 * 18;
    const int off2 = 80  + g2 * 10;
    const int off1 = g1 * 5;

    // -------------------------- staging --------------------------------
    auto stage = [&](int c, int buf) {
        #pragma unroll
        for (int u = 0; u < 9; u++) {            // 9*512 = 4608 = 8 rows * 576
            int idx = tid + u * THREADS;
            int r   = idx / IN4;
            int f   = idx - r * IN4;
            int rl  = c * CHUNK + r;
            if (rl < nrows) {
                float4* dst = Xs + (size_t)buf * (CHUNK * RS4) + r * RS4 + pad_map(f);
                const float* src = x + (size_t)(row0 + rl) * IN_DIM + f * 4;
                cpa16((uint32_t)__cvta_generic_to_shared(dst), src);
            }
        }
    };

    stage(0, 0);
    asm volatile("cp.async.commit_group;\n");

    for (int c = 0; c < nchunks; c++) {
        if (c + 1 < nchunks) stage(c + 1, (c + 1) & 1);
        asm volatile("cp.async.commit_group;\n");
        asm volatile("cp.async.wait_group 1;\n");
        __syncthreads();

        const float4* base = Xs + (size_t)(c & 1) * (CHUNK * RS4);
        const int rmax = min(CHUNK, nrows - c * CHUNK);
        #pragma unroll 1
        for (int r = 0; r < rmax; r++) {
            const float4* xr = base + r * RS4;
            float* orow = out + (size_t)(row0 + c * CHUNK + r) * OUT_DIM;

            if (is3) {
                // 8 LDS.128, 64 FMA (2 cols x half-K)
                float a0=0.f,a1=0.f,a2=0.f,a3=0.f, e0=0.f,e1=0.f,e2=0.f,e3=0.f;
                #pragma unroll
                for (int k4 = 0; k4 < 8; k4++) {
                    float4 xv = xr[off3 + 2 * k4 + h];
                    a0 = fmaf(xv.x, wa[4*k4+0], a0);
                    a1 = fmaf(xv.y, wa[4*k4+1], a1);
                    a2 = fmaf(xv.z, wa[4*k4+2], a2);
                    a3 = fmaf(xv.w, wa[4*k4+3], a3);
                    e0 = fmaf(xv.x, wb[4*k4+0], e0);
                    e1 = fmaf(xv.y, wb[4*k4+1], e1);
                    e2 = fmaf(xv.z, wb[4*k4+2], e2);
                    e3 = fmaf(xv.w, wb[4*k4+3], e3);
                }
                float sA = (a0 + a1) + (a2 + a3);
                float sB = (e0 + e1) + (e2 + e3);
                sA += __shfl_xor_sync(0xffffffffu, sA, 1);
                sB += __shfl_xor_sync(0xffffffffu, sB, 1);
                if (h == 0) orow[colA] = sA + bA;
                else        orow[colB] = sB + bB;
            } else {
                // seg2: 4 LDS.128, 32 FMA
                float a0=0.f,a1=0.f,a2=0.f,a3=0.f, e0=0.f,e1=0.f,e2=0.f,e3=0.f;
                #pragma unroll
                for (int k4 = 0; k4 < 4; k4++) {
                    float4 xv = xr[off2 + 2 * k4 + h];
                    a0 = fmaf(xv.x, wa[4*k4+0], a0);
                    a1 = fmaf(xv.y, wa[4*k4+1], a1);
                    a2 = fmaf(xv.z, wa[4*k4+2], a2);
                    a3 = fmaf(xv.w, wa[4*k4+3], a3);
                    e0 = fmaf(xv.x, wb[4*k4+0], e0);
                    e1 = fmaf(xv.y, wb[4*k4+1], e1);
                    e2 = fmaf(xv.z, wb[4*k4+2], e2);
                    e3 = fmaf(xv.w, wb[4*k4+3], e3);
                }
                float sA = (a0 + a1) + (a2 + a3);
                float sB = (e0 + e1) + (e2 + e3);
                sA += __shfl_xor_sync(0xffffffffu, sA, 1);
                sB += __shfl_xor_sync(0xffffffffu, sB, 1);
                if (h == 0) orow[colA] = sA + bA;
                else        orow[colB] = sB + bB;

                if (is1) {
                    // seg1: 2 LDS.128, 16 FMA
                    float q0=0.f,q1=0.f,q2=0.f,q3=0.f, t0=0.f,t1=0.f,t2=0.f,t3=0.f;
                    #pragma unroll
                    for (int k4 = 0; k4 < 2; k4++) {
                        float4 xv = xr[off1 + 2 * k4 + h];
                        q0 = fmaf(xv.x, wc[4*k4+0], q0);
                        q1 = fmaf(xv.y, wc[4*k4+1], q1);
                        q2 = fmaf(xv.z, wc[4*k4+2], q2);
                        q3 = fmaf(xv.w, wc[4*k4+3], q3);
                        t0 = fmaf(xv.x, wd[4*k4+0], t0);
                        t1 = fmaf(xv.y, wd[4*k4+1], t1);
                        t2 = fmaf(xv.z, wd[4*k4+2], t2);
                        t3 = fmaf(xv.w, wd[4*k4+3], t3);
                    }
                    float sC = (q0 + q1) + (q2 + q3);
                    float sD = (t0 + t1) + (t2 + t3);
                    sC += __shfl_xor_sync(0xffffffffu, sC, 1);
                    sD += __shfl_xor_sync(0xffffffffu, sD, 1);
                    if (h == 0) orow[colC] = sC + bC;
                    else        orow[colD] = sD + bD;
                }
            }
        }
        __syncthreads();
    }
}

extern "C" void kernel_launch(void* const* d_in, const int* in_sizes, int n_in,
                              void* d_out, int out_size)
{
    const float* x    = (const float*)d_in[0];
    const float* wflt = (const float*)d_in[1];
    const float* bias = (const float*)d_in[2];
    float* out        = (float*)d_out;

    cudaFuncSetAttribute(tet_kernel, cudaFuncAttributeMaxDynamicSharedMemorySize, SMEM_BYTES);
    tet_kernel<<<NCTA, THREADS, SMEM_BYTES>>>(x, wflt, bias, out);
}

// round 5
// speedup vs baseline: 1.9246x; 1.1261x over previous
#include <cuda_runtime.h>
#include <cstdint>

#define THREADS 576
#define IN_DIM  2304
#define OUT_DIM 576
#define BATCH   16384
#define IN4     576                 // float4 per compact x row
#define RS4     688                 // padded row stride in float4
#define CHUNK   8                   // rows per chunk
#define NCTA    148
#define XBUF_F4 (CHUNK * RS4)       // 5504 float4 per buffer
#define XS_BYTES (2 * XBUF_F4 * 16)            // 176128
#define SMEM_BYTES (XS_BYTES + CHUNK * OUT_DIM * 4)  // +18432 = 194560

// Padded smem row layout (float4 indices within one x row):
//   seg1: 16 groups, stride 5  -> [0, 80)
//   seg2: 32 groups, stride 10 -> [80, 400)
//   seg3: 16 groups, stride 18 -> [400, 688)
__device__ __forceinline__ int pad_map(int f) {
    if (f < 64)  return f + (f >> 2);
    if (f < 320) return 80 + (f - 64) + (((f - 64) >> 3) << 1);
    return 400 + (f - 320) + (((f - 320) >> 4) << 1);
}

__device__ __forceinline__ void cpa16(uint32_t daddr, const void* src) {
    asm volatile("cp.async.cg.shared.global [%0], [%1], 16;\n" :: "r"(daddr), "l"(src));
}

// one column-pair dot over this thread's K-half: N4 f4 loads, 8*N4 FMAs
#define DOTPAIR(N4)                                                        \
    {                                                                      \
        float a0=0.f,a1=0.f,a2=0.f,a3=0.f, e0=0.f,e1=0.f,e2=0.f,e3=0.f;    \
        _Pragma("unroll")                                                  \
        for (int k4 = 0; k4 < (N4); k4++) {                                \
            float4 xv = xr[xoff + 2 * k4 + h];                             \
            a0 = fmaf(xv.x, wA[4*k4+0], a0);                               \
            a1 = fmaf(xv.y, wA[4*k4+1], a1);                               \
            a2 = fmaf(xv.z, wA[4*k4+2], a2);                               \
            a3 = fmaf(xv.w, wA[4*k4+3], a3);                               \
            e0 = fmaf(xv.x, wB[4*k4+0], e0);                               \
            e1 = fmaf(xv.y, wB[4*k4+1], e1);                               \
            e2 = fmaf(xv.z, wB[4*k4+2], e2);                               \
            e3 = fmaf(xv.w, wB[4*k4+3], e3);                               \
        }                                                                  \
        sA = (a0 + a1) + (a2 + a3);                                        \
        sB = (e0 + e1) + (e2 + e3);                                        \
    }

extern "C" __global__ void __launch_bounds__(THREADS, 1)
tet_kernel(const float* __restrict__ x, const float* __restrict__ w,
           const float* __restrict__ bias, float* __restrict__ out)
{
    extern __shared__ __align__(16) float4 Xs[];          // [2][CHUNK][RS4]
    float* Os = (float*)(Xs + 2 * XBUF_F4);               // [CHUNK][OUT_DIM]

    const int tid = threadIdx.x;
    const int bid = blockIdx.x;

    // row partition: 16384 = 148*110 + 104
    const int row0  = bid * 110 + (bid < 104 ? bid : 104);
    const int nrows = 110 + (bid < 104 ? 1 : 0);
    const int nchunks = (nrows + CHUNK - 1) / CHUNK;      // 14

    const int h = tid & 1;          // K-half parity (partner = tid^1)

    // ---- role setup: tid<256 seg3 | tid<512 seg2 | else seg1 ----
    float wA[32], wB[32];
    int xoff, myCol;
    if (tid < 256) {
        const int p = tid >> 1, g3 = p >> 3, cp3 = p & 7;
        const int base = 9216 + g3 * 1024;
        #pragma unroll
        for (int k4 = 0; k4 < 8; k4++)
            #pragma unroll
            for (int i = 0; i < 4; i++) {
                int k = 8 * k4 + 4 * h + i;
                wA[4*k4+i] = w[base + k * 16 + cp3];
                wB[4*k4+i] = w[base + k * 16 + cp3 + 8];
            }
        xoff = 400 + 18 * g3;
        const int colA = 320 + g3 * 16 + cp3;
        myCol = h ? colA + 8 : colA;
    } else if (tid < 512) {
        const int p = (tid - 256) >> 1, g2 = p >> 2, cp2 = p & 3;
        const int base = 1024 + g2 * 256;
        #pragma unroll
        for (int k4 = 0; k4 < 4; k4++)
            #pragma unroll
            for (int i = 0; i < 4; i++) {
                int k = 8 * k4 + 4 * h + i;
                wA[4*k4+i] = w[base + k * 8 + cp2];
                wB[4*k4+i] = w[base + k * 8 + cp2 + 4];
            }
        xoff = 80 + 10 * g2;
        const int colA = 64 + g2 * 8 + cp2;
        myCol = h ? colA + 4 : colA;
    } else {
        const int p = (tid - 512) >> 1, g1 = p >> 1, cp1 = p & 1;
        const int base = g1 * 64;
        #pragma unroll
        for (int k4 = 0; k4 < 2; k4++)
            #pragma unroll
            for (int i = 0; i < 4; i++) {
                int k = 8 * k4 + 4 * h + i;
                wA[4*k4+i] = w[base + k * 4 + cp1];
                wB[4*k4+i] = w[base + k * 4 + cp1 + 2];
            }
        xoff = 5 * g1;
        const int colA = g1 * 4 + cp1;
        myCol = h ? colA + 2 : colA;
    }
    const float myBias = bias[myCol];

    // ---- staging constants: idx = tid + u*576 -> r = u, f = tid ----
    const uint32_t xsAddr = (uint32_t)__cvta_generic_to_shared(Xs);
    const uint32_t dstPad = xsAddr + (uint32_t)pad_map(tid) * 16;
    const char* srcBase = (const char*)(x + (size_t)row0 * IN_DIM) + (size_t)tid * 16;

    auto stage = [&](int cc) {
        const uint32_t d0 = dstPad + (uint32_t)(cc & 1) * (XBUF_F4 * 16);
        const char* s0 = srcBase + (size_t)cc * (CHUNK * IN_DIM * 4);
        const int umax = min(CHUNK, nrows - cc * CHUNK);
        #pragma unroll
        for (int u = 0; u < CHUNK; u++)
            if (u < umax) cpa16(d0 + u * (RS4 * 16), s0 + (size_t)u * (IN_DIM * 4));
    };

    // flush mapping: 1152 f4 over 576 threads, 2 per thread
    const int frow = tid / 144;            // 0..3
    const int fcol = tid - frow * 144;     // 0..143
    float4* out4 = (float4*)out;

    stage(0);
    asm volatile("cp.async.commit_group;\n");

    for (int c = 0; c < nchunks; c++) {
        if (c + 1 < nchunks) stage(c + 1);
        asm volatile("cp.async.commit_group;\n");
        asm volatile("cp.async.wait_group 1;\n");
        __syncthreads();

        const float4* bufp = Xs + (size_t)(c & 1) * XBUF_F4;
        const int rmax = min(CHUNK, nrows - c * CHUNK);

        #pragma unroll 1
        for (int r = 0; r < rmax; r++) {
            const float4* xr = bufp + r * RS4;
            float sA, sB;
            if (tid < 256)      DOTPAIR(8)
            else if (tid < 512) DOTPAIR(4)
            else                DOTPAIR(2)
            sA += __shfl_xor_sync(0xffffffffu, sA, 1);
            sB += __shfl_xor_sync(0xffffffffu, sB, 1);
            Os[r * OUT_DIM + myCol] = (h ? sB : sA) + myBias;
        }
        __syncthreads();

        // coalesced flush: Os -> out (STG.128)
        #pragma unroll
        for (int j = 0; j < 2; j++) {
            int r = frow + 4 * j;
            if (r < rmax)
                out4[(size_t)(row0 + c * CHUNK + r) * 144 + fcol] =
                    *(const float4*)&Os[r * OUT_DIM + fcol * 4];
        }
    }
}

extern "C" void kernel_launch(void* const* d_in, const int* in_sizes, int n_in,
                              void* d_out, int out_size)
{
    const float* x    = (const float*)d_in[0];
    const float* wflt = (const float*)d_in[1];
    const float* bias = (const float*)d_in[2];
    float* out        = (float*)d_out;

    cudaFuncSetAttribute(tet_kernel, cudaFuncAttributeMaxDynamicSharedMemorySize, SMEM_BYTES);
    tet_kernel<<<NCTA, THREADS, SMEM_BYTES>>>(x, wflt, bias, out);
}

// round 6
// speedup vs baseline: 2.4026x; 1.2484x over previous
#include <cuda_runtime.h>
#include <cstdint>

#define THREADS 576
#define IN_DIM  2304
#define OUT_DIM 576
#define BATCH   16384
#define RS4     688                 // padded row stride in float4
#define CHUNK   8                   // rows per chunk
#define NCTA    148
#define XBUF_F4 (CHUNK * RS4)       // 5504 float4 per buffer
#define SMEM_BYTES (2 * XBUF_F4 * 16)   // 176128

// Padded smem row layout (float4 indices within one x row):
//   seg1: 16 groups, stride 5  -> [0, 80)
//   seg2: 32 groups, stride 10 -> [80, 400)
//   seg3: 16 groups, stride 18 -> [400, 688)
__device__ __forceinline__ int pad_map(int f) {
    if (f < 64)  return f + (f >> 2);
    if (f < 320) return 80 + (f - 64) + (((f - 64) >> 3) << 1);
    return 400 + (f - 320) + (((f - 320) >> 4) << 1);
}

__device__ __forceinline__ void cpa16(uint32_t daddr, const void* src) {
    asm volatile("cp.async.cg.shared.global [%0], [%1], 16;\n" :: "r"(daddr), "l"(src));
}

// Two rows, one column pair each, over this thread's K-half.
// N4 f4 loads per row; 8*N4 FMAs per row. 2 accumulators per output.
#define DOTPAIR2(N4)                                                         \
    {                                                                        \
        float a0=0.f,a1=0.f, e0=0.f,e1=0.f, f0=0.f,f1=0.f, g0=0.f,g1=0.f;    \
        _Pragma("unroll")                                                    \
        for (int k4 = 0; k4 < (N4); k4++) {                                  \
            float4 u = xr0[xoff + 2 * k4 + h];                               \
            float4 v = xr1[xoff + 2 * k4 + h];                               \
            a0 = fmaf(u.x, wA[4*k4+0], a0);                                  \
            a1 = fmaf(u.y, wA[4*k4+1], a1);                                  \
            a0 = fmaf(u.z, wA[4*k4+2], a0);                                  \
            a1 = fmaf(u.w, wA[4*k4+3], a1);                                  \
            e0 = fmaf(u.x, wB[4*k4+0], e0);                                  \
            e1 = fmaf(u.y, wB[4*k4+1], e1);                                  \
            e0 = fmaf(u.z, wB[4*k4+2], e0);                                  \
            e1 = fmaf(u.w, wB[4*k4+3], e1);                                  \
            f0 = fmaf(v.x, wA[4*k4+0], f0);                                  \
            f1 = fmaf(v.y, wA[4*k4+1], f1);                                  \
            f0 = fmaf(v.z, wA[4*k4+2], f0);                                  \
            f1 = fmaf(v.w, wA[4*k4+3], f1);                                  \
            g0 = fmaf(v.x, wB[4*k4+0], g0);                                  \
            g1 = fmaf(v.y, wB[4*k4+1], g1);                                  \
            g0 = fmaf(v.z, wB[4*k4+2], g0);                                  \
            g1 = fmaf(v.w, wB[4*k4+3], g1);                                  \
        }                                                                    \
        sA0 = a0 + a1; sB0 = e0 + e1; sA1 = f0 + f1; sB1 = g0 + g1;          \
    }

extern "C" __global__ void __launch_bounds__(THREADS, 1)
tet_kernel(const float* __restrict__ x, const float* __restrict__ w,
           const float* __restrict__ bias, float* __restrict__ out)
{
    extern __shared__ __align__(16) float4 Xs[];          // [2][CHUNK][RS4]

    const int tid = threadIdx.x;
    const int bid = blockIdx.x;

    // row partition: 16384 = 148*110 + 104
    const int row0  = bid * 110 + (bid < 104 ? bid : 104);
    const int nrows = 110 + (bid < 104 ? 1 : 0);
    const int nchunks = (nrows + CHUNK - 1) / CHUNK;      // 14

    const int h = tid & 1;          // K-half parity (partner = tid^1)

    // ---- role setup: tid<256 seg3 | tid<512 seg2 | else seg1 ----
    // Each warp's 32 outputs per row form one contiguous 128B span of out.
    float wA[32], wB[32];
    int xoff, myCol;
    if (tid < 256) {
        const int p = tid >> 1, g3 = p >> 3, cp3 = p & 7;
        const int base = 9216 + g3 * 1024;
        #pragma unroll
        for (int k4 = 0; k4 < 8; k4++)
            #pragma unroll
            for (int i = 0; i < 4; i++) {
                int k = 8 * k4 + 4 * h + i;
                wA[4*k4+i] = w[base + k * 16 + cp3];
                wB[4*k4+i] = w[base + k * 16 + cp3 + 8];
            }
        xoff = 400 + 18 * g3;
        const int colA = 320 + g3 * 16 + cp3;
        myCol = h ? colA + 8 : colA;
    } else if (tid < 512) {
        const int p = (tid - 256) >> 1, g2 = p >> 2, cp2 = p & 3;
        const int base = 1024 + g2 * 256;
        #pragma unroll
        for (int k4 = 0; k4 < 4; k4++)
            #pragma unroll
            for (int i = 0; i < 4; i++) {
                int k = 8 * k4 + 4 * h + i;
                wA[4*k4+i] = w[base + k * 8 + cp2];
                wB[4*k4+i] = w[base + k * 8 + cp2 + 4];
            }
        xoff = 80 + 10 * g2;
        const int colA = 64 + g2 * 8 + cp2;
        myCol = h ? colA + 4 : colA;
    } else {
        const int p = (tid - 512) >> 1, g1 = p >> 1, cp1 = p & 1;
        const int base = g1 * 64;
        #pragma unroll
        for (int k4 = 0; k4 < 2; k4++)
            #pragma unroll
            for (int i = 0; i < 4; i++) {
                int k = 8 * k4 + 4 * h + i;
                wA[4*k4+i] = w[base + k * 4 + cp1];
                wB[4*k4+i] = w[base + k * 4 + cp1 + 2];
            }
        xoff = 5 * g1;
        const int colA = g1 * 4 + cp1;
        myCol = h ? colA + 2 : colA;
    }
    const float myBias = bias[myCol];

    // ---- staging: idx = tid + u*576 -> r = u, f = tid (all addresses static) ----
    const uint32_t xsAddr = (uint32_t)__cvta_generic_to_shared(Xs);
    const uint32_t dstPad = xsAddr + (uint32_t)pad_map(tid) * 16;
    const char* srcBase = (const char*)(x + (size_t)row0 * IN_DIM) + (size_t)tid * 16;

    auto stage = [&](int cc) {
        const uint32_t d0 = dstPad + (uint32_t)(cc & 1) * (XBUF_F4 * 16);
        const char* s0 = srcBase + (size_t)cc * (CHUNK * IN_DIM * 4);
        const int umax = min(CHUNK, nrows - cc * CHUNK);
        #pragma unroll
        for (int u = 0; u < CHUNK; u++)
            if (u < umax) cpa16(d0 + u * (RS4 * 16), s0 + (size_t)u * (IN_DIM * 4));
    };

    stage(0);
    asm volatile("cp.async.commit_group;\n");

    for (int c = 0; c < nchunks; c++) {
        // all committed groups done (== group c; c+1 not yet committed)
        asm volatile("cp.async.wait_group 0;\n");
        // single barrier: makes chunk-c data visible to all threads AND
        // separates everyone's compute(c-1) reads from stage(c+1) writes.
        __syncthreads();
        if (c + 1 < nchunks) {
            stage(c + 1);
            asm volatile("cp.async.commit_group;\n");
        }

        const float4* bufp = Xs + (size_t)(c & 1) * XBUF_F4;
        const int rmax = min(CHUNK, nrows - c * CHUNK);
        float* ob = out + (size_t)(row0 + c * CHUNK) * OUT_DIM;

        #pragma unroll
        for (int r = 0; r < CHUNK; r += 2) {
            if (r >= rmax) break;
            const float4* xr0 = bufp + r * RS4;
            const float4* xr1 = xr0 + RS4;       // may read junk if r+1>=rmax (unused)
            float sA0, sB0, sA1, sB1;
            if (tid < 256)      DOTPAIR2(8)
            else if (tid < 512) DOTPAIR2(4)
            else                DOTPAIR2(2)
            sA0 += __shfl_xor_sync(0xffffffffu, sA0, 1);
            sB0 += __shfl_xor_sync(0xffffffffu, sB0, 1);
            sA1 += __shfl_xor_sync(0xffffffffu, sA1, 1);
            sB1 += __shfl_xor_sync(0xffffffffu, sB1, 1);
            float r0v = (h ? sB0 : sA0) + myBias;
            float r1v = (h ? sB1 : sA1) + myBias;
            ob[(size_t)r * OUT_DIM + myCol] = r0v;
            if (r + 1 < rmax) ob[(size_t)(r + 1) * OUT_DIM + myCol] = r1v;
        }
    }
}

extern "C" void kernel_launch(void* const* d_in, const int* in_sizes, int n_in,
                              void* d_out, int out_size)
{
    const float* x    = (const float*)d_in[0];
    const float* wflt = (const float*)d_in[1];
    const float* bias = (const float*)d_in[2];
    float* out        = (float*)d_out;

    cudaFuncSetAttribute(tet_kernel, cudaFuncAttributeMaxDynamicSharedMemorySize, SMEM_BYTES);
    tet_kernel<<<NCTA, THREADS, SMEM_BYTES>>>(x, wflt, bias, out);
}